// round 16
// baseline (speedup 1.0000x reference)
#include <cuda_runtime.h>
#include <math.h>

// Per-batch affine coefficients: A00, A01, A11 (A10 = A01, translation = 0).
__device__ float4 g_A[256];
// Per-row conservative in-bounds interval [x, y) in output-w pixels.
__device__ int2 g_bounds[65536];

// One thread per output row (b,h): computes A (redundantly, cheap) and the
// conservative w-interval where the bilinear footprint can touch the image.
// Outside it, all 4 tap weights are provably zero. A is written by h==0.
__global__ void rows_kernel(const float* __restrict__ thetas,
                            const float* __restrict__ l1s,
                            const float* __restrict__ l2s,
                            int B, int H, int W) {
    int r = blockIdx.x * blockDim.x + threadIdx.x;
    if (r < B * H) {
        int b = r / H, h = r - b * H;
        float c, s;
        __sincosf(thetas[b], &s, &c);
        float i1 = 1.0f / l1s[b];
        float i2 = 1.0f / l2s[b];
        float A00 = c * c * i1 + s * s * i2;
        float A01 = c * s * (i1 - i2);
        float A11 = s * s * i1 + c * c * i2;
        if (h == 0) g_A[b] = make_float4(A00, A01, A11, 0.0f);

        float fW = (float)W, fH = (float)H;
        float yn = ((float)h + 0.5f) * (2.0f / fH) - 1.0f;
        float xn0 = (0.5f) * (2.0f / fW) - 1.0f;          // xn at w=0
        // gx(w) = slope_x*w + c1 ; gy(w) = slope_y*w + c2  (pixel coords)
        float c1 = (A00 * xn0 + A01 * yn + 1.0f) * (fW * 0.5f) - 0.5f;
        float c2 = (A01 * xn0 + A11 * yn + 1.0f) * (fH * 0.5f) - 0.5f;
        float slope_x = A00;                 // > 0 always (pos.def.)
        float slope_y = A01 * fH / fW;

        float lo = 0.0f, hi = fW;
        // gx in (-1, W)
        lo = fmaxf(lo, (-1.0f - c1) / slope_x - 1.0f);
        hi = fminf(hi, (fW - c1) / slope_x + 1.0f);
        // gy in (-1, H)
        if (fabsf(slope_y) > 1e-5f) {
            float r0 = (-1.0f - c2) / slope_y;
            float r1 = (fH - c2) / slope_y;
            lo = fmaxf(lo, fminf(r0, r1) - 1.0f);
            hi = fminf(hi, fmaxf(r0, r1) + 1.0f);
        } else if (!(c2 > -2.0f && c2 < fH + 1.0f)) {
            lo = 0.0f; hi = 0.0f;            // whole row OOB
        }
        int wlo = max(0, (int)floorf(lo));
        int whi = min(W, (int)ceilf(hi) + 1);
        if (whi < wlo) whi = wlo;
        g_bounds[r] = make_int2(wlo, whi);
    }
    __threadfence();
#if __CUDA_ARCH__ >= 900
    cudaTriggerProgrammaticLaunchCompletion();
#endif
}

// One thread = 1 output pixel x 3 channels; 256x1 row strips.
// Threads outside the row's precomputed interval store zeros with no math.
__global__ __launch_bounds__(256)
void warp_kernel(const float* __restrict__ x, float* __restrict__ out,
                 int H, int W) {
#if __CUDA_ARCH__ >= 900
    cudaGridDependencySynchronize();
#endif
    const int b = blockIdx.z;
    const int h = blockIdx.y;
    const int w = blockIdx.x * 256 + threadIdx.x;
    if (w >= W) return;

    const int HW = H * W;
    float* op = out + (long long)(b * 3) * HW + h * W + w;

    const int2 bnd = g_bounds[b * H + h];     // broadcast load
    if (w < bnd.x || w >= bnd.y) {
        __stcs(op, 0.0f);
        __stcs(op + HW, 0.0f);
        __stcs(op + 2 * HW, 0.0f);
        return;
    }

    const float4 A = g_A[b];

    float xn = ((float)w + 0.5f) * (2.0f / (float)W) - 1.0f;
    float yn = ((float)h + 0.5f) * (2.0f / (float)H) - 1.0f;
    float gx = (A.x * xn + A.y * yn + 1.0f) * ((float)W * 0.5f) - 0.5f;
    float gy = (A.y * xn + A.z * yn + 1.0f) * ((float)H * 0.5f) - 0.5f;

    // exact per-pixel authority (interval is conservative)
    if (!(gx > -1.0f) || gx >= (float)W || !(gy > -1.0f) || gy >= (float)H) {
        __stcs(op, 0.0f);
        __stcs(op + HW, 0.0f);
        __stcs(op + 2 * HW, 0.0f);
        return;
    }

    float x0f = floorf(gx), y0f = floorf(gy);
    int x0 = (int)x0f, y0 = (int)y0f;
    int x1 = x0 + 1, y1 = y0 + 1;
    float wx1 = gx - x0f, wx0 = 1.0f - wx1;
    float wy1 = gy - y0f, wy0 = 1.0f - wy1;

    // in-bounds guarantees from early-out: x0 < W, x1 >= 0, y0 < H, y1 >= 0
    float fx0 = (x0 >= 0) ? wx0 : 0.0f;
    float fx1 = (x1 < W) ? wx1 : 0.0f;
    float fy0 = (y0 >= 0) ? wy0 : 0.0f;
    float fy1 = (y1 < H) ? wy1 : 0.0f;

    int xc0 = max(x0, 0);
    int xc1 = min(x1, W - 1);
    int yc0 = max(y0, 0);
    int yc1 = min(y1, H - 1);

    int o00 = yc0 * W + xc0;
    int o01 = yc0 * W + xc1;
    int o10 = yc1 * W + xc0;
    int o11 = yc1 * W + xc1;

    float w00 = fy0 * fx0, w01 = fy0 * fx1;
    float w10 = fy1 * fx0, w11 = fy1 * fx1;

    const float* p0 = x + (long long)(b * 3) * HW;
    const float* p1 = p0 + HW;
    const float* p2 = p1 + HW;

    // 12 independent gathers -> max MLP
    float v000 = __ldg(p0 + o00), v001 = __ldg(p0 + o01);
    float v010 = __ldg(p0 + o10), v011 = __ldg(p0 + o11);
    float v100 = __ldg(p1 + o00), v101 = __ldg(p1 + o01);
    float v110 = __ldg(p1 + o10), v111 = __ldg(p1 + o11);
    float v200 = __ldg(p2 + o00), v201 = __ldg(p2 + o01);
    float v210 = __ldg(p2 + o10), v211 = __ldg(p2 + o11);

    __stcs(op,          w00 * v000 + w01 * v001 + w10 * v010 + w11 * v011);
    __stcs(op + HW,     w00 * v100 + w01 * v101 + w10 * v110 + w11 * v111);
    __stcs(op + 2 * HW, w00 * v200 + w01 * v201 + w10 * v210 + w11 * v211);
}

extern "C" void kernel_launch(void* const* d_in, const int* in_sizes, int n_in,
                              void* d_out, int out_size) {
    const float* x      = (const float*)d_in[0];
    const float* thetas = (const float*)d_in[1];
    const float* l1s    = (const float*)d_in[2];
    const float* l2s    = (const float*)d_in[3];
    float* out = (float*)d_out;

    int B = in_sizes[1];
    long long hw = (long long)in_sizes[0] / ((long long)B * 3);
    int W = (int)(sqrt((double)hw) + 0.5);
    int H = (int)(hw / W);

    int rows = B * H;
    rows_kernel<<<(rows + 255) / 256, 256>>>(thetas, l1s, l2s, B, H, W);

    dim3 block(256, 1, 1);
    dim3 grid((W + 255) / 256, H, B);

    // PDL: overlap warp_kernel launch with rows_kernel; device-side
    // cudaGridDependencySynchronize() orders the g_A / g_bounds reads.
    cudaLaunchConfig_t cfg = {};
    cfg.gridDim = grid;
    cfg.blockDim = block;
    cfg.dynamicSmemBytes = 0;
    cfg.stream = 0;
    cudaLaunchAttribute attr[1];
    attr[0].id = cudaLaunchAttributeProgrammaticStreamSerialization;
    attr[0].val.programmaticStreamSerializationAllowed = 1;
    cfg.attrs = attr;
    cfg.numAttrs = 1;

    cudaError_t err = cudaLaunchKernelEx(&cfg, warp_kernel, x, out, H, W);
    if (err != cudaSuccess) {
        warp_kernel<<<grid, block>>>(x, out, H, W);
    }
}